// round 13
// baseline (speedup 1.0000x reference)
#include <cuda_runtime.h>
#include <cuda_fp16.h>
#include <math.h>

#define NN   50000
#define EE   1600000
#define DIN  128
#define HIDD 128
#define DOUT 64
#define NLL  200000
#define NEG  0.2f

#define SCAN_B 512
#define NBLK   ((NN + SCAN_B - 1) / SCAN_B)   // 98
#define GEMM_BLOCKS ((NN + 127) / 128)        // 391
#define E4_BLOCKS   ((EE / 4 + 255) / 256)    // 1563
#define FIN_BLOCKS  ((NN + 255) / 256)        // 196
#define DEC_BLOCKS  (((NLL + 3) / 4 * 32 + 255) / 256)
#define ZERO_BLOCKS 32

// ---------------- scratch (device globals; no allocation allowed) ----------------
__device__ float  g_bufB[NN * HIDD];   // agg output (fp32) = next GEMM input
__device__ __half g_h16[NN * HIDD];    // fp16 GEMM output (gather source; fp32 C is dead)
__device__ float  g_zbuf[NN * DOUT];
__device__ float  g_as[NN];
__device__ float  g_ad[NN];
__device__ float  g_dinv[NN];
__device__ int    g_deg[NN];       // zero-initialized at load; re-zeroed by decode
__device__ int    g_cursor[NN];    // same
__device__ int    g_rowloc[NN];    // block-local exclusive scan
__device__ int    g_rowptr[NN + 1];
__device__ int    g_csrc[EE];
__device__ int    g_bsum[NBLK];

__device__ __forceinline__ float lrelu(float v) { return v > 0.f ? v : NEG * v; }

// packed f32x2 helpers
__device__ __forceinline__ unsigned long long pack2(float lo, float hi) {
    unsigned long long r;
    asm("mov.b64 %0, {%1, %2};" : "=l"(r) : "f"(lo), "f"(hi));
    return r;
}
__device__ __forceinline__ void unpack2(unsigned long long v, float& lo, float& hi) {
    asm("mov.b64 {%0, %1}, %2;" : "=f"(lo), "=f"(hi) : "l"(v));
}
__device__ __forceinline__ void fma2(unsigned long long& d,
                                     unsigned long long a, unsigned long long b) {
    asm("fma.rn.f32x2 %0, %1, %2, %0;" : "+l"(d) : "l"(a), "l"(b));
}

// ---------------- launch 1: per-block local scan (+bsum, +dinv) ----------------
__global__ void scan_partial_kernel() {
    __shared__ int ws[SCAN_B / 32];
    int tid = threadIdx.x;
    int lane = tid & 31, wid = tid >> 5;
    int i = blockIdx.x * SCAN_B + tid;
    int v = (i < NN) ? g_deg[i] : 0;
    if (i < NN) g_dinv[i] = rsqrtf((float)(v + 1));
    int x = v;
    #pragma unroll
    for (int o = 1; o < 32; o <<= 1) {
        int y = __shfl_up_sync(0xffffffffu, x, o);
        if (lane >= o) x += y;
    }
    if (lane == 31) ws[wid] = x;
    __syncthreads();
    if (tid < 32) {
        int w = (tid < SCAN_B / 32) ? ws[tid] : 0;
        #pragma unroll
        for (int o = 1; o < SCAN_B / 32; o <<= 1) {
            int y = __shfl_up_sync(0xffffffffu, w, o);
            if (tid >= o) w += y;
        }
        if (tid < SCAN_B / 32) ws[tid] = w;
    }
    __syncthreads();
    int pref = wid ? ws[wid - 1] : 0;
    int incl = x + pref;
    if (i < NN) g_rowloc[i] = incl - v;
    if (tid == SCAN_B - 1) g_bsum[blockIdx.x] = incl;
}

__device__ __forceinline__ void block_boff(int* s_boff, int* s_ws) {
    int tid = threadIdx.x;
    if (tid < 128) {
        int lane = tid & 31, w4 = tid >> 5;
        int v = (tid < NBLK) ? g_bsum[tid] : 0;
        int x = v;
        #pragma unroll
        for (int o = 1; o < 32; o <<= 1) {
            int y = __shfl_up_sync(0xffffffffu, x, o);
            if (lane >= o) x += y;
        }
        if (lane == 31) s_ws[w4] = x;
    }
    __syncthreads();
    if (tid < 32) {
        int w = (tid < 4) ? s_ws[tid] : 0;
        #pragma unroll
        for (int o = 1; o < 4; o <<= 1) {
            int y = __shfl_up_sync(0xffffffffu, w, o);
            if (tid >= o) w += y;
        }
        if (tid < 4) s_ws[tid] = w;
    }
    __syncthreads();
    if (tid < 128) {
        int lane = tid & 31, w4 = tid >> 5;
        int v = (tid < NBLK) ? g_bsum[tid] : 0;
        int x = v;
        #pragma unroll
        for (int o = 1; o < 32; o <<= 1) {
            int y = __shfl_up_sync(0xffffffffu, x, o);
            if (lane >= o) x += y;
        }
        int pref = w4 ? s_ws[w4 - 1] : 0;
        if (tid < NBLK) s_boff[tid] = x + pref - v;
    }
    __syncthreads();
}

// ---------------- launch 2: CSR fill + rowptr finalize ----------------
__global__ void fill_finalize_kernel(const int* __restrict__ src, const int* __restrict__ dst) {
    __shared__ int s_boff[NBLK];
    __shared__ int s_ws[4];
    block_boff(s_boff, s_ws);
    int tid = threadIdx.x;
    int b = blockIdx.x;
    if (b < E4_BLOCKS) {
        int i = b * 256 + tid;
        if (i < EE / 4) {
            int4 s = reinterpret_cast<const int4*>(src)[i];
            int4 d = reinterpret_cast<const int4*>(dst)[i];
            int p;
            p = atomicAdd(&g_cursor[d.x], 1); g_csrc[g_rowloc[d.x] + s_boff[d.x >> 9] + p] = s.x;
            p = atomicAdd(&g_cursor[d.y], 1); g_csrc[g_rowloc[d.y] + s_boff[d.y >> 9] + p] = s.y;
            p = atomicAdd(&g_cursor[d.z], 1); g_csrc[g_rowloc[d.z] + s_boff[d.z >> 9] + p] = s.z;
            p = atomicAdd(&g_cursor[d.w], 1); g_csrc[g_rowloc[d.w] + s_boff[d.w >> 9] + p] = s.w;
        }
    } else {
        int i = (b - E4_BLOCKS) * 256 + tid;
        if (i < NN) g_rowptr[i] = g_rowloc[i] + s_boff[i >> 9];
        if (b == E4_BLOCKS && tid == 0) g_rowptr[NN] = EE;
    }
}

// ---------------- SGEMM (FFMA2, double-buffered): fp16 shadow output (+ fused scores) ----------------
template<int BN, bool FUSE, bool COUNT>
__global__ __launch_bounds__(256)
void sgemm128_kernel(const float* __restrict__ A, const float* __restrict__ B,
                     const float* __restrict__ avs, const float* __restrict__ avd,
                     const int* __restrict__ edst) {
    if (COUNT && blockIdx.x >= GEMM_BLOCKS) {
        int bi = blockIdx.x - GEMM_BLOCKS;
        int i = bi * 256 + threadIdx.x;
        if (i < EE / 4) {
            int4 d = reinterpret_cast<const int4*>(edst)[i];
            atomicAdd(&g_deg[d.x], 1);
            atomicAdd(&g_deg[d.y], 1);
            atomicAdd(&g_deg[d.z], 1);
            atomicAdd(&g_deg[d.w], 1);
        }
        return;
    }
    constexpr int TN = BN / 16;
    constexpr int TN2 = TN / 2;
    constexpr int NB_LD = (BN == 128) ? 2 : 1;
    __shared__ float As[2][16][132];      // 16.5 KB
    __shared__ float Bs[2][16][BN];       // <=16 KB  (total 33 KB static, 2 blocks/SM)
    const int tid = threadIdx.x;
    const int block_row = blockIdx.x * 128;
    const int tr = tid >> 4;
    const int tc = tid & 15;

    unsigned long long acc2[8][TN2];
    #pragma unroll
    for (int i = 0; i < 8; i++)
        #pragma unroll
        for (int j = 0; j < TN2; j++) acc2[i][j] = 0ull;

    const int aRow = tid >> 2;               // 0..63
    const int aCol = (tid & 3) << 2;         // 0,4,8,12

    float4 sa[2], sb[NB_LD];

    auto ldg_tiles = [&](int k0) {
        #pragma unroll
        for (int i = 0; i < 2; i++) {
            int grow = block_row + aRow + i * 64;
            sa[i] = make_float4(0.f, 0.f, 0.f, 0.f);
            if (grow < NN)
                sa[i] = *reinterpret_cast<const float4*>(&A[(size_t)grow * 128 + k0 + aCol]);
        }
        if (BN == 128) {
            #pragma unroll
            for (int i = 0; i < NB_LD; i++) {
                int r = (tid >> 5) + i * 8;
                int c = (tid & 31) * 4;
                sb[i] = *reinterpret_cast<const float4*>(&B[(size_t)(k0 + r) * BN + c]);
            }
        } else {
            int r = tid >> 4;
            int c = (tid & 15) * 4;
            sb[0] = *reinterpret_cast<const float4*>(&B[(size_t)(k0 + r) * BN + c]);
        }
    };
    auto sts_tiles = [&](int buf) {
        #pragma unroll
        for (int i = 0; i < 2; i++) {
            int r = aRow + i * 64;
            As[buf][aCol + 0][r] = sa[i].x;
            As[buf][aCol + 1][r] = sa[i].y;
            As[buf][aCol + 2][r] = sa[i].z;
            As[buf][aCol + 3][r] = sa[i].w;
        }
        if (BN == 128) {
            #pragma unroll
            for (int i = 0; i < NB_LD; i++) {
                int r = (tid >> 5) + i * 8;
                int c = (tid & 31) * 4;
                *reinterpret_cast<float4*>(&Bs[buf][r][c]) = sb[i];
            }
        } else {
            int r = tid >> 4;
            int c = (tid & 15) * 4;
            *reinterpret_cast<float4*>(&Bs[buf][r][c]) = sb[0];
        }
    };

    // prologue: tile 0 -> buffer 0
    ldg_tiles(0);
    sts_tiles(0);
    __syncthreads();

    #pragma unroll 2
    for (int it = 0; it < 8; it++) {
        int cur = it & 1;
        if (it < 7) ldg_tiles((it + 1) * 16);      // LDG latency hidden under compute
        #pragma unroll
        for (int kk = 0; kk < 16; kk++) {
            float ra[8], rb[TN];
            *reinterpret_cast<float4*>(&ra[0]) = *reinterpret_cast<float4*>(&As[cur][kk][tr * 8]);
            *reinterpret_cast<float4*>(&ra[4]) = *reinterpret_cast<float4*>(&As[cur][kk][tr * 8 + 4]);
            #pragma unroll
            for (int j4 = 0; j4 < TN / 4; j4++)
                *reinterpret_cast<float4*>(&rb[j4 * 4]) =
                    *reinterpret_cast<float4*>(&Bs[cur][kk][tc * TN + j4 * 4]);
            unsigned long long bp[TN2];
            #pragma unroll
            for (int j = 0; j < TN2; j++) bp[j] = pack2(rb[2 * j], rb[2 * j + 1]);
            #pragma unroll
            for (int i = 0; i < 8; i++) {
                unsigned long long ap = pack2(ra[i], ra[i]);
                #pragma unroll
                for (int j = 0; j < TN2; j++)
                    fma2(acc2[i][j], ap, bp[j]);
            }
        }
        if (it < 7) sts_tiles(cur ^ 1);
        __syncthreads();
    }

    float acc[8][TN];
    #pragma unroll
    for (int i = 0; i < 8; i++)
        #pragma unroll
        for (int j = 0; j < TN2; j++)
            unpack2(acc2[i][j], acc[i][2 * j], acc[i][2 * j + 1]);

    // fp16-only epilogue store
    #pragma unroll
    for (int i = 0; i < 8; i++) {
        int grow = block_row + tr * 8 + i;
        if (grow < NN) {
            __half2 hp[TN2];
            #pragma unroll
            for (int j = 0; j < TN2; j++)
                hp[j] = __floats2half2_rn(acc[i][2 * j], acc[i][2 * j + 1]);
            if (TN == 8)
                *reinterpret_cast<uint4*>(&g_h16[(size_t)grow * BN + tc * TN]) =
                    *reinterpret_cast<uint4*>(hp);
            else
                *reinterpret_cast<uint2*>(&g_h16[(size_t)grow * BN + tc * TN]) =
                    *reinterpret_cast<uint2*>(hp);
        }
    }

    if (FUSE) {
        float avsr[TN], avdr[TN];
        #pragma unroll
        for (int j = 0; j < TN; j++) {
            avsr[j] = avs[tc * TN + j];
            avdr[j] = avd[tc * TN + j];
        }
        #pragma unroll
        for (int i = 0; i < 8; i++) {
            float s = 0.f, d = 0.f;
            #pragma unroll
            for (int j = 0; j < TN; j++) {
                s = fmaf(acc[i][j], avsr[j], s);
                d = fmaf(acc[i][j], avdr[j], d);
            }
            #pragma unroll
            for (int mk = 1; mk < 16; mk <<= 1) {
                s += __shfl_xor_sync(0xffffffffu, s, mk);
                d += __shfl_xor_sync(0xffffffffu, d, mk);
            }
            if (tc == 0) {
                int grow = block_row + tr * 8 + i;
                if (grow < NN) { g_as[grow] = s; g_ad[grow] = d; }
            }
        }
    }
}

// ---------------- GAT aggregate: single fused pass, fp16 row gather ----------------
__global__ __launch_bounds__(256)
void gat_agg_kernel(const float* __restrict__ bias,
                    float* __restrict__ out) {
    int warp = (blockIdx.x * blockDim.x + threadIdx.x) >> 5;
    int lane = threadIdx.x & 31;
    if (warp >= NN) return;
    int node = warp;
    int rs = g_rowptr[node], re = g_rowptr[node + 1];
    float adi = g_ad[node];
    float pself = __expf(lrelu(g_as[node] + adi));

    const uint2* h2 = reinterpret_cast<const uint2*>(g_h16);
    uint2 selfraw = h2[(size_t)node * 32 + lane];
    float2 sf01 = __half22float2(*reinterpret_cast<__half2*>(&selfraw.x));
    float2 sf23 = __half22float2(*reinterpret_cast<__half2*>(&selfraw.y));
    float4 acc = make_float4(pself * sf01.x, pself * sf01.y, pself * sf23.x, pself * sf23.y);
    float ssum_l = (lane == 0) ? pself : 0.f;

    for (int base = rs; base < re; base += 32) {
        int j = base + lane;
        int srcv = 0; float pv = 0.f;
        if (j < re) {
            srcv = g_csrc[j];
            pv = __expf(lrelu(g_as[srcv] + adi));
        }
        ssum_l += pv;
        int cnt = re - base;
        if (cnt >= 32) {
            #pragma unroll
            for (int t = 0; t < 32; t++) {
                int s = __shfl_sync(0xffffffffu, srcv, t);
                float p = __shfl_sync(0xffffffffu, pv, t);
                uint2 raw = h2[(size_t)s * 32 + lane];
                float2 f01 = __half22float2(*reinterpret_cast<__half2*>(&raw.x));
                float2 f23 = __half22float2(*reinterpret_cast<__half2*>(&raw.y));
                acc.x = fmaf(p, f01.x, acc.x);
                acc.y = fmaf(p, f01.y, acc.y);
                acc.z = fmaf(p, f23.x, acc.z);
                acc.w = fmaf(p, f23.y, acc.w);
            }
        } else {
            for (int t = 0; t < cnt; t++) {
                int s = __shfl_sync(0xffffffffu, srcv, t);
                float p = __shfl_sync(0xffffffffu, pv, t);
                uint2 raw = h2[(size_t)s * 32 + lane];
                float2 f01 = __half22float2(*reinterpret_cast<__half2*>(&raw.x));
                float2 f23 = __half22float2(*reinterpret_cast<__half2*>(&raw.y));
                acc.x = fmaf(p, f01.x, acc.x);
                acc.y = fmaf(p, f01.y, acc.y);
                acc.z = fmaf(p, f23.x, acc.z);
                acc.w = fmaf(p, f23.y, acc.w);
            }
        }
    }
    float ssum = ssum_l;
    #pragma unroll
    for (int o = 16; o; o >>= 1) ssum += __shfl_xor_sync(0xffffffffu, ssum, o);

    float inv = 1.f / ssum;
    float4 bv = reinterpret_cast<const float4*>(bias)[lane];
    float4 o;
    o.x = fmaxf(fmaf(acc.x, inv, bv.x), 0.f);
    o.y = fmaxf(fmaf(acc.y, inv, bv.y), 0.f);
    o.z = fmaxf(fmaf(acc.z, inv, bv.z), 0.f);
    o.w = fmaxf(fmaf(acc.w, inv, bv.w), 0.f);
    reinterpret_cast<float4*>(out)[(size_t)node * 32 + lane] = o;
}

// ---------------- GCN aggregate: fp16 gather (4 B/lane/edge), OUT=64 ----------------
__global__ __launch_bounds__(256)
void gcn_agg_kernel(const float* __restrict__ bias,
                    float* __restrict__ z) {
    int warp = (blockIdx.x * blockDim.x + threadIdx.x) >> 5;
    int lane = threadIdx.x & 31;
    if (warp >= NN) return;
    int node = warp;
    int rs = g_rowptr[node], re = g_rowptr[node + 1];
    float di = g_dinv[node];
    const unsigned int* h1 = reinterpret_cast<const unsigned int*>(g_h16);
    unsigned int selfraw = h1[(size_t)node * 32 + lane];
    float2 gv = __half22float2(*reinterpret_cast<__half2*>(&selfraw));
    float nself = di * di;
    float2 acc = make_float2(nself * gv.x, nself * gv.y);
    for (int base = rs; base < re; base += 32) {
        int j = base + lane;
        int srcv = 0; float dv = 0.f;
        if (j < re) { srcv = g_csrc[j]; dv = g_dinv[srcv]; }
        int cnt = re - base;
        if (cnt >= 32) {
            #pragma unroll
            for (int t = 0; t < 32; t++) {
                int s = __shfl_sync(0xffffffffu, srcv, t);
                float nd = __shfl_sync(0xffffffffu, dv, t);
                float nrm = di * nd;
                unsigned int raw = h1[(size_t)s * 32 + lane];
                float2 v = __half22float2(*reinterpret_cast<__half2*>(&raw));
                acc.x = fmaf(nrm, v.x, acc.x);
                acc.y = fmaf(nrm, v.y, acc.y);
            }
        } else {
            for (int t = 0; t < cnt; t++) {
                int s = __shfl_sync(0xffffffffu, srcv, t);
                float nd = __shfl_sync(0xffffffffu, dv, t);
                float nrm = di * nd;
                unsigned int raw = h1[(size_t)s * 32 + lane];
                float2 v = __half22float2(*reinterpret_cast<__half2*>(&raw));
                acc.x = fmaf(nrm, v.x, acc.x);
                acc.y = fmaf(nrm, v.y, acc.y);
            }
        }
    }
    float2 bv = reinterpret_cast<const float2*>(bias)[lane];
    reinterpret_cast<float2*>(z)[(size_t)node * 32 + lane] =
        make_float2(acc.x + bv.x, acc.y + bv.y);
}

// ---------------- decode + re-zero of deg/cursor ----------------
__global__ void decode_kernel(const int* __restrict__ eli, float* __restrict__ out) {
    if (blockIdx.x >= DEC_BLOCKS) {
        int i = (blockIdx.x - DEC_BLOCKS) * 256 + threadIdx.x;
        for (int k = i; k < NN; k += ZERO_BLOCKS * 256) { g_deg[k] = 0; g_cursor[k] = 0; }
        return;
    }
    int gtid = blockIdx.x * blockDim.x + threadIdx.x;
    int warp = gtid >> 5;
    int lane = threadIdx.x & 31;
    int sub = lane >> 3, l8 = lane & 7;
    int e = warp * 4 + sub;
    if (e >= NLL) return;
    int a = eli[e];
    int b = eli[NLL + e];
    const float4* z4 = reinterpret_cast<const float4*>(g_zbuf);
    float4 va0 = z4[(size_t)a * 16 + l8];
    float4 va1 = z4[(size_t)a * 16 + 8 + l8];
    float4 vb0 = z4[(size_t)b * 16 + l8];
    float4 vb1 = z4[(size_t)b * 16 + 8 + l8];
    float dot = va0.x * vb0.x + va0.y * vb0.y + va0.z * vb0.z + va0.w * vb0.w
              + va1.x * vb1.x + va1.y * vb1.y + va1.z * vb1.z + va1.w * vb1.w;
    dot += __shfl_xor_sync(0xffffffffu, dot, 4);
    dot += __shfl_xor_sync(0xffffffffu, dot, 2);
    dot += __shfl_xor_sync(0xffffffffu, dot, 1);
    if (l8 == 0) out[e] = dot;
}

// ---------------- launch ----------------
extern "C" void kernel_launch(void* const* d_in, const int* in_sizes, int n_in,
                              void* d_out, int out_size) {
    const float* x   = (const float*)d_in[0];
    const int*   ei  = (const int*)d_in[1];          // [2,E]
    const int*   eli = (const int*)d_in[2];          // [2,NL]
    const float* W1  = (const float*)d_in[3];
    const float* a1s = (const float*)d_in[4];
    const float* a1d = (const float*)d_in[5];
    const float* b1  = (const float*)d_in[6];
    const float* W2  = (const float*)d_in[7];
    const float* a2s = (const float*)d_in[8];
    const float* a2d = (const float*)d_in[9];
    const float* b2  = (const float*)d_in[10];
    const float* W3  = (const float*)d_in[11];
    const float* a3s = (const float*)d_in[12];
    const float* a3d = (const float*)d_in[13];
    const float* b3  = (const float*)d_in[14];
    const float* W4  = (const float*)d_in[15];
    const float* b4  = (const float*)d_in[16];
    float* out = (float*)d_out;

    const int* e_src = ei;
    const int* e_dst = ei + EE;

    float *bufB, *zbuf;
    cudaGetSymbolAddress((void**)&bufB, g_bufB);
    cudaGetSymbolAddress((void**)&zbuf, g_zbuf);

    const int TB = 256;
    int node_warp_blocks = (NN * 32 + TB - 1) / TB;

    // 0: sgemm1 + fused degree-count (writes h16 + scores only)
    sgemm128_kernel<HIDD, true, true><<<GEMM_BLOCKS + E4_BLOCKS, 256>>>(x, W1, a1s, a1d, e_dst);
    // 1: per-block local scan (+dinv, +bsum)
    scan_partial_kernel<<<NBLK, SCAN_B>>>();
    // 2: CSR fill + rowptr finalize
    fill_finalize_kernel<<<E4_BLOCKS + FIN_BLOCKS, TB>>>(e_src, e_dst);
    // 3: gat layer 1  <- profiled launch index (control: expect ~51us unchanged)
    gat_agg_kernel<<<node_warp_blocks, TB>>>(b1, bufB);

    // layer 2
    sgemm128_kernel<HIDD, true, false><<<GEMM_BLOCKS, 256>>>(bufB, W2, a2s, a2d, nullptr);
    gat_agg_kernel<<<node_warp_blocks, TB>>>(b2, bufB);

    // layer 3
    sgemm128_kernel<HIDD, true, false><<<GEMM_BLOCKS, 256>>>(bufB, W3, a3s, a3d, nullptr);
    gat_agg_kernel<<<node_warp_blocks, TB>>>(b3, bufB);

    // GCN
    sgemm128_kernel<DOUT, false, false><<<GEMM_BLOCKS, 256>>>(bufB, W4, nullptr, nullptr, nullptr);
    gcn_agg_kernel<<<node_warp_blocks, TB>>>(b4, zbuf);

    // decode + re-zero deg/cursor
    decode_kernel<<<DEC_BLOCKS + ZERO_BLOCKS, TB>>>(eli, out);
}

// round 14
// speedup vs baseline: 1.0796x; 1.0796x over previous
#include <cuda_runtime.h>
#include <cuda_fp16.h>
#include <math.h>

#define NN   50000
#define EE   1600000
#define DIN  128
#define HIDD 128
#define DOUT 64
#define NLL  200000
#define NEG  0.2f

#define SCAN_B 512
#define NBLK   ((NN + SCAN_B - 1) / SCAN_B)   // 98
#define GEMM_BLOCKS ((NN + 127) / 128)        // 391
#define E4_BLOCKS   ((EE / 4 + 255) / 256)    // 1563
#define FIN_BLOCKS  ((NN + 255) / 256)        // 196
#define DEC_BLOCKS  (((NLL + 3) / 4 * 32 + 255) / 256)
#define ZERO_BLOCKS 32

// ---------------- scratch (device globals; no allocation allowed) ----------------
__device__ float  g_bufB[NN * HIDD];   // agg output (fp32) = next GEMM input
__device__ __half g_h16[NN * HIDD];    // fp16 GEMM output (gather source)
__device__ float  g_zbuf[NN * DOUT];
__device__ float  g_as[NN];
__device__ float  g_ad[NN];
__device__ float  g_dinv[NN];
__device__ int    g_deg[NN];       // zero-initialized at load; re-zeroed by decode
__device__ int    g_cursor[NN];    // same
__device__ int    g_rowloc[NN];
__device__ int    g_rowptr[NN + 1];
__device__ int    g_csrc[EE];
__device__ int    g_bsum[NBLK];

__device__ __forceinline__ float lrelu(float v) { return v > 0.f ? v : NEG * v; }

// packed f32x2 helpers
__device__ __forceinline__ unsigned long long pack2(float lo, float hi) {
    unsigned long long r;
    asm("mov.b64 %0, {%1, %2};" : "=l"(r) : "f"(lo), "f"(hi));
    return r;
}
__device__ __forceinline__ void unpack2(unsigned long long v, float& lo, float& hi) {
    asm("mov.b64 {%0, %1}, %2;" : "=f"(lo), "=f"(hi) : "l"(v));
}
__device__ __forceinline__ void fma2(unsigned long long& d,
                                     unsigned long long a, unsigned long long b) {
    asm("fma.rn.f32x2 %0, %1, %2, %0;" : "+l"(d) : "l"(a), "l"(b));
}

// ---------------- launch 1: per-block local scan (+bsum, +dinv) ----------------
__global__ void scan_partial_kernel() {
    __shared__ int ws[SCAN_B / 32];
    int tid = threadIdx.x;
    int lane = tid & 31, wid = tid >> 5;
    int i = blockIdx.x * SCAN_B + tid;
    int v = (i < NN) ? g_deg[i] : 0;
    if (i < NN) g_dinv[i] = rsqrtf((float)(v + 1));
    int x = v;
    #pragma unroll
    for (int o = 1; o < 32; o <<= 1) {
        int y = __shfl_up_sync(0xffffffffu, x, o);
        if (lane >= o) x += y;
    }
    if (lane == 31) ws[wid] = x;
    __syncthreads();
    if (tid < 32) {
        int w = (tid < SCAN_B / 32) ? ws[tid] : 0;
        #pragma unroll
        for (int o = 1; o < SCAN_B / 32; o <<= 1) {
            int y = __shfl_up_sync(0xffffffffu, w, o);
            if (tid >= o) w += y;
        }
        if (tid < SCAN_B / 32) ws[tid] = w;
    }
    __syncthreads();
    int pref = wid ? ws[wid - 1] : 0;
    int incl = x + pref;
    if (i < NN) g_rowloc[i] = incl - v;
    if (tid == SCAN_B - 1) g_bsum[blockIdx.x] = incl;
}

__device__ __forceinline__ void block_boff(int* s_boff, int* s_ws) {
    int tid = threadIdx.x;
    if (tid < 128) {
        int lane = tid & 31, w4 = tid >> 5;
        int v = (tid < NBLK) ? g_bsum[tid] : 0;
        int x = v;
        #pragma unroll
        for (int o = 1; o < 32; o <<= 1) {
            int y = __shfl_up_sync(0xffffffffu, x, o);
            if (lane >= o) x += y;
        }
        if (lane == 31) s_ws[w4] = x;
    }
    __syncthreads();
    if (tid < 32) {
        int w = (tid < 4) ? s_ws[tid] : 0;
        #pragma unroll
        for (int o = 1; o < 4; o <<= 1) {
            int y = __shfl_up_sync(0xffffffffu, w, o);
            if (tid >= o) w += y;
        }
        if (tid < 4) s_ws[tid] = w;
    }
    __syncthreads();
    if (tid < 128) {
        int lane = tid & 31, w4 = tid >> 5;
        int v = (tid < NBLK) ? g_bsum[tid] : 0;
        int x = v;
        #pragma unroll
        for (int o = 1; o < 32; o <<= 1) {
            int y = __shfl_up_sync(0xffffffffu, x, o);
            if (lane >= o) x += y;
        }
        int pref = w4 ? s_ws[w4 - 1] : 0;
        if (tid < NBLK) s_boff[tid] = x + pref - v;
    }
    __syncthreads();
}

// ---------------- launch 2: CSR fill + rowptr finalize ----------------
__global__ void fill_finalize_kernel(const int* __restrict__ src, const int* __restrict__ dst) {
    __shared__ int s_boff[NBLK];
    __shared__ int s_ws[4];
    block_boff(s_boff, s_ws);
    int tid = threadIdx.x;
    int b = blockIdx.x;
    if (b < E4_BLOCKS) {
        int i = b * 256 + tid;
        if (i < EE / 4) {
            int4 s = reinterpret_cast<const int4*>(src)[i];
            int4 d = reinterpret_cast<const int4*>(dst)[i];
            int p;
            p = atomicAdd(&g_cursor[d.x], 1); g_csrc[g_rowloc[d.x] + s_boff[d.x >> 9] + p] = s.x;
            p = atomicAdd(&g_cursor[d.y], 1); g_csrc[g_rowloc[d.y] + s_boff[d.y >> 9] + p] = s.y;
            p = atomicAdd(&g_cursor[d.z], 1); g_csrc[g_rowloc[d.z] + s_boff[d.z >> 9] + p] = s.z;
            p = atomicAdd(&g_cursor[d.w], 1); g_csrc[g_rowloc[d.w] + s_boff[d.w >> 9] + p] = s.w;
        }
    } else {
        int i = (b - E4_BLOCKS) * 256 + tid;
        if (i < NN) g_rowptr[i] = g_rowloc[i] + s_boff[i >> 9];
        if (b == E4_BLOCKS && tid == 0) g_rowptr[NN] = EE;
    }
}

// ---------------- SGEMM (FFMA2, single-buffer — R12 proven): fp16 shadow output ----------------
template<int BN, bool FUSE, bool COUNT>
__global__ __launch_bounds__(256)
void sgemm128_kernel(const float* __restrict__ A, const float* __restrict__ B,
                     const float* __restrict__ avs, const float* __restrict__ avd,
                     const int* __restrict__ edst) {
    if (COUNT && blockIdx.x >= GEMM_BLOCKS) {
        int bi = blockIdx.x - GEMM_BLOCKS;
        int i = bi * 256 + threadIdx.x;
        if (i < EE / 4) {
            int4 d = reinterpret_cast<const int4*>(edst)[i];
            atomicAdd(&g_deg[d.x], 1);
            atomicAdd(&g_deg[d.y], 1);
            atomicAdd(&g_deg[d.z], 1);
            atomicAdd(&g_deg[d.w], 1);
        }
        return;
    }
    constexpr int TN = BN / 16;
    constexpr int TN2 = TN / 2;
    __shared__ float As[16][132];
    __shared__ float Bs[16][BN];
    const int tid = threadIdx.x;
    const int block_row = blockIdx.x * 128;
    const int tr = tid >> 4;
    const int tc = tid & 15;

    unsigned long long acc2[8][TN2];
    #pragma unroll
    for (int i = 0; i < 8; i++)
        #pragma unroll
        for (int j = 0; j < TN2; j++) acc2[i][j] = 0ull;

    const int aRow = tid >> 2;
    const int aCol = (tid & 3) << 2;

    #pragma unroll 2
    for (int k0 = 0; k0 < 128; k0 += 16) {
        #pragma unroll
        for (int i = 0; i < 2; i++) {
            int r = aRow + i * 64;
            int grow = block_row + r;
            float4 v = make_float4(0.f, 0.f, 0.f, 0.f);
            if (grow < NN)
                v = *reinterpret_cast<const float4*>(&A[(size_t)grow * 128 + k0 + aCol]);
            As[aCol + 0][r] = v.x;
            As[aCol + 1][r] = v.y;
            As[aCol + 2][r] = v.z;
            As[aCol + 3][r] = v.w;
        }
        if (BN == 128) {
            #pragma unroll
            for (int i = 0; i < 2; i++) {
                int r = (tid >> 5) + i * 8;
                int c = (tid & 31) * 4;
                *reinterpret_cast<float4*>(&Bs[r][c]) =
                    *reinterpret_cast<const float4*>(&B[(size_t)(k0 + r) * BN + c]);
            }
        } else {
            int r = tid >> 4;
            int c = (tid & 15) * 4;
            *reinterpret_cast<float4*>(&Bs[r][c]) =
                *reinterpret_cast<const float4*>(&B[(size_t)(k0 + r) * BN + c]);
        }
        __syncthreads();
        #pragma unroll
        for (int kk = 0; kk < 16; kk++) {
            float ra[8], rb[TN];
            *reinterpret_cast<float4*>(&ra[0]) = *reinterpret_cast<float4*>(&As[kk][tr * 8]);
            *reinterpret_cast<float4*>(&ra[4]) = *reinterpret_cast<float4*>(&As[kk][tr * 8 + 4]);
            #pragma unroll
            for (int j4 = 0; j4 < TN / 4; j4++)
                *reinterpret_cast<float4*>(&rb[j4 * 4]) =
                    *reinterpret_cast<float4*>(&Bs[kk][tc * TN + j4 * 4]);
            unsigned long long bp[TN2];
            #pragma unroll
            for (int j = 0; j < TN2; j++) bp[j] = pack2(rb[2 * j], rb[2 * j + 1]);
            #pragma unroll
            for (int i = 0; i < 8; i++) {
                unsigned long long ap = pack2(ra[i], ra[i]);
                #pragma unroll
                for (int j = 0; j < TN2; j++)
                    fma2(acc2[i][j], ap, bp[j]);
            }
        }
        __syncthreads();
    }

    float acc[8][TN];
    #pragma unroll
    for (int i = 0; i < 8; i++)
        #pragma unroll
        for (int j = 0; j < TN2; j++)
            unpack2(acc2[i][j], acc[i][2 * j], acc[i][2 * j + 1]);

    // fp16-only epilogue store
    #pragma unroll
    for (int i = 0; i < 8; i++) {
        int grow = block_row + tr * 8 + i;
        if (grow < NN) {
            __half2 hp[TN2];
            #pragma unroll
            for (int j = 0; j < TN2; j++)
                hp[j] = __floats2half2_rn(acc[i][2 * j], acc[i][2 * j + 1]);
            if (TN == 8)
                *reinterpret_cast<uint4*>(&g_h16[(size_t)grow * BN + tc * TN]) =
                    *reinterpret_cast<uint4*>(hp);
            else
                *reinterpret_cast<uint2*>(&g_h16[(size_t)grow * BN + tc * TN]) =
                    *reinterpret_cast<uint2*>(hp);
        }
    }

    if (FUSE) {
        float avsr[TN], avdr[TN];
        #pragma unroll
        for (int j = 0; j < TN; j++) {
            avsr[j] = avs[tc * TN + j];
            avdr[j] = avd[tc * TN + j];
        }
        #pragma unroll
        for (int i = 0; i < 8; i++) {
            float s = 0.f, d = 0.f;
            #pragma unroll
            for (int j = 0; j < TN; j++) {
                s = fmaf(acc[i][j], avsr[j], s);
                d = fmaf(acc[i][j], avdr[j], d);
            }
            #pragma unroll
            for (int mk = 1; mk < 16; mk <<= 1) {
                s += __shfl_xor_sync(0xffffffffu, s, mk);
                d += __shfl_xor_sync(0xffffffffu, d, mk);
            }
            if (tc == 0) {
                int grow = block_row + tr * 8 + i;
                if (grow < NN) { g_as[grow] = s; g_ad[grow] = d; }
            }
        }
    }
}

// ---------------- GAT aggregate: single fused pass, fp16 gather, smem-staged (s,p) ----------------
__global__ __launch_bounds__(256)
void gat_agg_kernel(const float* __restrict__ bias,
                    float* __restrict__ out) {
    __shared__ float2 s_sp[8][32];    // per-warp staged (src, p) — replaces 2 shfls with 1 LDS.64
    int warp = (blockIdx.x * blockDim.x + threadIdx.x) >> 5;
    int w = (threadIdx.x >> 5);
    int lane = threadIdx.x & 31;
    if (warp >= NN) return;
    int node = warp;
    int rs = g_rowptr[node], re = g_rowptr[node + 1];
    float adi = g_ad[node];
    float pself = __expf(lrelu(g_as[node] + adi));

    const uint2* h2 = reinterpret_cast<const uint2*>(g_h16);
    uint2 selfraw = h2[(size_t)node * 32 + lane];
    float2 sf01 = __half22float2(*reinterpret_cast<__half2*>(&selfraw.x));
    float2 sf23 = __half22float2(*reinterpret_cast<__half2*>(&selfraw.y));
    float4 acc = make_float4(pself * sf01.x, pself * sf01.y, pself * sf23.x, pself * sf23.y);
    float ssum_l = (lane == 0) ? pself : 0.f;

    for (int base = rs; base < re; base += 32) {
        int j = base + lane;
        int srcv = 0; float pv = 0.f;
        if (j < re) {
            srcv = g_csrc[j];
            pv = __expf(lrelu(g_as[srcv] + adi));
        }
        ssum_l += pv;
        __syncwarp();                         // previous chunk's reads complete
        s_sp[w][lane] = make_float2(__int_as_float(srcv), pv);
        __syncwarp();                         // stores visible to all lanes
        int cnt = re - base;
        if (cnt >= 32) {
            #pragma unroll
            for (int t = 0; t < 32; t++) {
                float2 sp = s_sp[w][t];
                int s = __float_as_int(sp.x);
                float p = sp.y;
                uint2 raw = h2[(size_t)s * 32 + lane];
                float2 f01 = __half22float2(*reinterpret_cast<__half2*>(&raw.x));
                float2 f23 = __half22float2(*reinterpret_cast<__half2*>(&raw.y));
                acc.x = fmaf(p, f01.x, acc.x);
                acc.y = fmaf(p, f01.y, acc.y);
                acc.z = fmaf(p, f23.x, acc.z);
                acc.w = fmaf(p, f23.y, acc.w);
            }
        } else {
            for (int t = 0; t < cnt; t++) {
                float2 sp = s_sp[w][t];
                int s = __float_as_int(sp.x);
                float p = sp.y;
                uint2 raw = h2[(size_t)s * 32 + lane];
                float2 f01 = __half22float2(*reinterpret_cast<__half2*>(&raw.x));
                float2 f23 = __half22float2(*reinterpret_cast<__half2*>(&raw.y));
                acc.x = fmaf(p, f01.x, acc.x);
                acc.y = fmaf(p, f01.y, acc.y);
                acc.z = fmaf(p, f23.x, acc.z);
                acc.w = fmaf(p, f23.y, acc.w);
            }
        }
    }
    float ssum = ssum_l;
    #pragma unroll
    for (int o = 16; o; o >>= 1) ssum += __shfl_xor_sync(0xffffffffu, ssum, o);

    float inv = 1.f / ssum;
    float4 bv = reinterpret_cast<const float4*>(bias)[lane];
    float4 o;
    o.x = fmaxf(fmaf(acc.x, inv, bv.x), 0.f);
    o.y = fmaxf(fmaf(acc.y, inv, bv.y), 0.f);
    o.z = fmaxf(fmaf(acc.z, inv, bv.z), 0.f);
    o.w = fmaxf(fmaf(acc.w, inv, bv.w), 0.f);
    reinterpret_cast<float4*>(out)[(size_t)node * 32 + lane] = o;
}

// ---------------- GCN aggregate: fp16 gather, smem-staged (s,nrm), OUT=64 ----------------
__global__ __launch_bounds__(256)
void gcn_agg_kernel(const float* __restrict__ bias,
                    float* __restrict__ z) {
    __shared__ float2 s_sp[8][32];
    int warp = (blockIdx.x * blockDim.x + threadIdx.x) >> 5;
    int w = (threadIdx.x >> 5);
    int lane = threadIdx.x & 31;
    if (warp >= NN) return;
    int node = warp;
    int rs = g_rowptr[node], re = g_rowptr[node + 1];
    float di = g_dinv[node];
    const unsigned int* h1 = reinterpret_cast<const unsigned int*>(g_h16);
    unsigned int selfraw = h1[(size_t)node * 32 + lane];
    float2 gv = __half22float2(*reinterpret_cast<__half2*>(&selfraw));
    float nself = di * di;
    float2 acc = make_float2(nself * gv.x, nself * gv.y);
    for (int base = rs; base < re; base += 32) {
        int j = base + lane;
        int srcv = 0; float nrm = 0.f;
        if (j < re) { srcv = g_csrc[j]; nrm = di * g_dinv[srcv]; }
        __syncwarp();
        s_sp[w][lane] = make_float2(__int_as_float(srcv), nrm);
        __syncwarp();
        int cnt = re - base;
        if (cnt >= 32) {
            #pragma unroll
            for (int t = 0; t < 32; t++) {
                float2 sp = s_sp[w][t];
                int s = __float_as_int(sp.x);
                float p = sp.y;
                unsigned int raw = h1[(size_t)s * 32 + lane];
                float2 v = __half22float2(*reinterpret_cast<__half2*>(&raw));
                acc.x = fmaf(p, v.x, acc.x);
                acc.y = fmaf(p, v.y, acc.y);
            }
        } else {
            for (int t = 0; t < cnt; t++) {
                float2 sp = s_sp[w][t];
                int s = __float_as_int(sp.x);
                float p = sp.y;
                unsigned int raw = h1[(size_t)s * 32 + lane];
                float2 v = __half22float2(*reinterpret_cast<__half2*>(&raw));
                acc.x = fmaf(p, v.x, acc.x);
                acc.y = fmaf(p, v.y, acc.y);
            }
        }
    }
    float2 bv = reinterpret_cast<const float2*>(bias)[lane];
    reinterpret_cast<float2*>(z)[(size_t)node * 32 + lane] =
        make_float2(acc.x + bv.x, acc.y + bv.y);
}

// ---------------- decode + re-zero of deg/cursor ----------------
__global__ void decode_kernel(const int* __restrict__ eli, float* __restrict__ out) {
    if (blockIdx.x >= DEC_BLOCKS) {
        int i = (blockIdx.x - DEC_BLOCKS) * 256 + threadIdx.x;
        for (int k = i; k < NN; k += ZERO_BLOCKS * 256) { g_deg[k] = 0; g_cursor[k] = 0; }
        return;
    }
    int gtid = blockIdx.x * blockDim.x + threadIdx.x;
    int warp = gtid >> 5;
    int lane = threadIdx.x & 31;
    int sub = lane >> 3, l8 = lane & 7;
    int e = warp * 4 + sub;
    if (e >= NLL) return;
    int a = eli[e];
    int b = eli[NLL + e];
    const float4* z4 = reinterpret_cast<const float4*>(g_zbuf);
    float4 va0 = z4[(size_t)a * 16 + l8];
    float4 va1 = z4[(size_t)a * 16 + 8 + l8];
    float4 vb0 = z4[(size_t)b * 16 + l8];
    float4 vb1 = z4[(size_t)b * 16 + 8 + l8];
    float dot = va0.x * vb0.x + va0.y * vb0.y + va0.z * vb0.z + va0.w * vb0.w
              + va1.x * vb1.x + va1.y * vb1.y + va1.z * vb1.z + va1.w * vb1.w;
    dot += __shfl_xor_sync(0xffffffffu, dot, 4);
    dot += __shfl_xor_sync(0xffffffffu, dot, 2);
    dot += __shfl_xor_sync(0xffffffffu, dot, 1);
    if (l8 == 0) out[e] = dot;
}

// ---------------- launch ----------------
extern "C" void kernel_launch(void* const* d_in, const int* in_sizes, int n_in,
                              void* d_out, int out_size) {
    const float* x   = (const float*)d_in[0];
    const int*   ei  = (const int*)d_in[1];          // [2,E]
    const int*   eli = (const int*)d_in[2];          // [2,NL]
    const float* W1  = (const float*)d_in[3];
    const float* a1s = (const float*)d_in[4];
    const float* a1d = (const float*)d_in[5];
    const float* b1  = (const float*)d_in[6];
    const float* W2  = (const float*)d_in[7];
    const float* a2s = (const float*)d_in[8];
    const float* a2d = (const float*)d_in[9];
    const float* b2  = (const float*)d_in[10];
    const float* W3  = (const float*)d_in[11];
    const float* a3s = (const float*)d_in[12];
    const float* a3d = (const float*)d_in[13];
    const float* b3  = (const float*)d_in[14];
    const float* W4  = (const float*)d_in[15];
    const float* b4  = (const float*)d_in[16];
    float* out = (float*)d_out;

    const int* e_src = ei;
    const int* e_dst = ei + EE;

    float *bufB, *zbuf;
    cudaGetSymbolAddress((void**)&bufB, g_bufB);
    cudaGetSymbolAddress((void**)&zbuf, g_zbuf);

    const int TB = 256;
    int node_warp_blocks = (NN * 32 + TB - 1) / TB;

    // 0: sgemm1 + fused degree-count (writes h16 + scores only)
    sgemm128_kernel<HIDD, true, true><<<GEMM_BLOCKS + E4_BLOCKS, 256>>>(x, W1, a1s, a1d, e_dst);
    // 1: per-block local scan (+dinv, +bsum)
    scan_partial_kernel<<<NBLK, SCAN_B>>>();
    // 2: CSR fill + rowptr finalize
    fill_finalize_kernel<<<E4_BLOCKS + FIN_BLOCKS, TB>>>(e_src, e_dst);
    // 3: gat layer 1  <- profiled launch index
    gat_agg_kernel<<<node_warp_blocks, TB>>>(b1, bufB);

    // layer 2
    sgemm128_kernel<HIDD, true, false><<<GEMM_BLOCKS, 256>>>(bufB, W2, a2s, a2d, nullptr);
    gat_agg_kernel<<<node_warp_blocks, TB>>>(b2, bufB);

    // layer 3
    sgemm128_kernel<HIDD, true, false><<<GEMM_BLOCKS, 256>>>(bufB, W3, a3s, a3d, nullptr);
    gat_agg_kernel<<<node_warp_blocks, TB>>>(b3, bufB);

    // GCN
    sgemm128_kernel<DOUT, false, false><<<GEMM_BLOCKS, 256>>>(bufB, W4, nullptr, nullptr, nullptr);
    gcn_agg_kernel<<<node_warp_blocks, TB>>>(b4, zbuf);

    // decode + re-zero deg/cursor
    decode_kernel<<<DEC_BLOCKS + ZERO_BLOCKS, TB>>>(eli, out);
}

// round 15
// speedup vs baseline: 1.3586x; 1.2584x over previous
#include <cuda_runtime.h>
#include <cuda_fp16.h>
#include <math.h>

#define NN   50000
#define EE   1600000
#define DIN  128
#define HIDD 128
#define DOUT 64
#define NLL  200000
#define NEG  0.2f

#define SCAN_B 512
#define NBLK   ((NN + SCAN_B - 1) / SCAN_B)   // 98
#define GEMM_BLOCKS ((NN + 127) / 128)        // 391
#define E4_BLOCKS   ((EE / 4 + 255) / 256)    // 1563
#define FIN_BLOCKS  ((NN + 255) / 256)        // 196
#define CVT_BLOCKS  ((NN * 128 / 8 + 255) / 256)  // 3125
#define DEC_BLOCKS  (((NLL + 3) / 4 * 32 + 255) / 256)
#define ZERO_BLOCKS 32

// ---------------- scratch (device globals; no allocation allowed) ----------------
__device__ __half g_a16[NN * HIDD];    // fp16 GEMM input (x16 or agg output)
__device__ __half g_h16[NN * HIDD];    // fp16 GEMM output (gather/scores source)
__device__ float  g_zbuf[NN * DOUT];
__device__ float  g_as[NN];
__device__ float  g_ad[NN];
__device__ float  g_dinv[NN];
__device__ int    g_deg[NN];       // zero-initialized at load; re-zeroed by decode
__device__ int    g_cursor[NN];    // same
__device__ int    g_rowloc[NN];
__device__ int    g_rowptr[NN + 1];
__device__ int    g_csrc[EE];
__device__ int    g_bsum[NBLK];

__device__ __forceinline__ float lrelu(float v) { return v > 0.f ? v : NEG * v; }
__device__ __forceinline__ unsigned int smem_u32(const void* p) {
    return (unsigned int)__cvta_generic_to_shared(p);
}

// ---------------- launch 0: degree count + x -> fp16 conversion ----------------
__global__ void prep_kernel(const float* __restrict__ x, const int* __restrict__ edst) {
    int b = blockIdx.x;
    int tid = threadIdx.x;
    if (b < E4_BLOCKS) {
        int i = b * 256 + tid;
        if (i < EE / 4) {
            int4 d = reinterpret_cast<const int4*>(edst)[i];
            atomicAdd(&g_deg[d.x], 1);
            atomicAdd(&g_deg[d.y], 1);
            atomicAdd(&g_deg[d.z], 1);
            atomicAdd(&g_deg[d.w], 1);
        }
        return;
    }
    int i = (b - E4_BLOCKS) * 256 + tid;     // each converts 8 floats
    if (i < NN * 128 / 8) {
        float4 f0 = reinterpret_cast<const float4*>(x)[i * 2];
        float4 f1 = reinterpret_cast<const float4*>(x)[i * 2 + 1];
        __half2 h0 = __floats2half2_rn(f0.x, f0.y);
        __half2 h1 = __floats2half2_rn(f0.z, f0.w);
        __half2 h2 = __floats2half2_rn(f1.x, f1.y);
        __half2 h3 = __floats2half2_rn(f1.z, f1.w);
        uint4 v;
        v.x = *(unsigned int*)&h0; v.y = *(unsigned int*)&h1;
        v.z = *(unsigned int*)&h2; v.w = *(unsigned int*)&h3;
        reinterpret_cast<uint4*>(g_a16)[i] = v;
    }
}

// ---------------- launch 1: per-block local scan (+bsum, +dinv) ----------------
__global__ void scan_partial_kernel() {
    __shared__ int ws[SCAN_B / 32];
    int tid = threadIdx.x;
    int lane = tid & 31, wid = tid >> 5;
    int i = blockIdx.x * SCAN_B + tid;
    int v = (i < NN) ? g_deg[i] : 0;
    if (i < NN) g_dinv[i] = rsqrtf((float)(v + 1));
    int x = v;
    #pragma unroll
    for (int o = 1; o < 32; o <<= 1) {
        int y = __shfl_up_sync(0xffffffffu, x, o);
        if (lane >= o) x += y;
    }
    if (lane == 31) ws[wid] = x;
    __syncthreads();
    if (tid < 32) {
        int w = (tid < SCAN_B / 32) ? ws[tid] : 0;
        #pragma unroll
        for (int o = 1; o < SCAN_B / 32; o <<= 1) {
            int y = __shfl_up_sync(0xffffffffu, w, o);
            if (tid >= o) w += y;
        }
        if (tid < SCAN_B / 32) ws[tid] = w;
    }
    __syncthreads();
    int pref = wid ? ws[wid - 1] : 0;
    int incl = x + pref;
    if (i < NN) g_rowloc[i] = incl - v;
    if (tid == SCAN_B - 1) g_bsum[blockIdx.x] = incl;
}

__device__ __forceinline__ void block_boff(int* s_boff, int* s_ws) {
    int tid = threadIdx.x;
    if (tid < 128) {
        int lane = tid & 31, w4 = tid >> 5;
        int v = (tid < NBLK) ? g_bsum[tid] : 0;
        int x = v;
        #pragma unroll
        for (int o = 1; o < 32; o <<= 1) {
            int y = __shfl_up_sync(0xffffffffu, x, o);
            if (lane >= o) x += y;
        }
        if (lane == 31) s_ws[w4] = x;
    }
    __syncthreads();
    if (tid < 32) {
        int w = (tid < 4) ? s_ws[tid] : 0;
        #pragma unroll
        for (int o = 1; o < 4; o <<= 1) {
            int y = __shfl_up_sync(0xffffffffu, w, o);
            if (tid >= o) w += y;
        }
        if (tid < 4) s_ws[tid] = w;
    }
    __syncthreads();
    if (tid < 128) {
        int lane = tid & 31, w4 = tid >> 5;
        int v = (tid < NBLK) ? g_bsum[tid] : 0;
        int x = v;
        #pragma unroll
        for (int o = 1; o < 32; o <<= 1) {
            int y = __shfl_up_sync(0xffffffffu, x, o);
            if (lane >= o) x += y;
        }
        int pref = w4 ? s_ws[w4 - 1] : 0;
        if (tid < NBLK) s_boff[tid] = x + pref - v;
    }
    __syncthreads();
}

// ---------------- launch 2: CSR fill + rowptr finalize ----------------
__global__ void fill_finalize_kernel(const int* __restrict__ src, const int* __restrict__ dst) {
    __shared__ int s_boff[NBLK];
    __shared__ int s_ws[4];
    block_boff(s_boff, s_ws);
    int tid = threadIdx.x;
    int b = blockIdx.x;
    if (b < E4_BLOCKS) {
        int i = b * 256 + tid;
        if (i < EE / 4) {
            int4 s = reinterpret_cast<const int4*>(src)[i];
            int4 d = reinterpret_cast<const int4*>(dst)[i];
            int p;
            p = atomicAdd(&g_cursor[d.x], 1); g_csrc[g_rowloc[d.x] + s_boff[d.x >> 9] + p] = s.x;
            p = atomicAdd(&g_cursor[d.y], 1); g_csrc[g_rowloc[d.y] + s_boff[d.y >> 9] + p] = s.y;
            p = atomicAdd(&g_cursor[d.z], 1); g_csrc[g_rowloc[d.z] + s_boff[d.z >> 9] + p] = s.z;
            p = atomicAdd(&g_cursor[d.w], 1); g_csrc[g_rowloc[d.w] + s_boff[d.w >> 9] + p] = s.w;
        }
    } else {
        int i = (b - E4_BLOCKS) * 256 + tid;
        if (i < NN) g_rowptr[i] = g_rowloc[i] + s_boff[i >> 9];
        if (b == E4_BLOCKS && tid == 0) g_rowptr[NN] = EE;
    }
}

// ---------------- HGEMM: g_h16[M,BN] = g_a16[M,128] * W[128,BN], mma.sync fp16->fp32 ----------------
// Tile 128xBN, 8 warps (warp tile 32 x BN/2). K staged in 2 chunks of 64.
// smem swizzle: 8-half chunk index XOR (row & 7) -> conflict-free LDSM.
template<int BN>
__global__ __launch_bounds__(256)
void hgemm_kernel(const float* __restrict__ W) {
    constexpr int KC = 64;
    constexpr int WN = BN / 2;
    constexpr int NT = WN / 8;
    __shared__ __align__(16) __half sA[128][KC];
    __shared__ __align__(16) __half sB[KC][BN];
    int tid = threadIdx.x;
    int wid = tid >> 5, lane = tid & 31;
    int warp_m = wid & 3, warp_n = wid >> 2;
    int block_row = blockIdx.x * 128;

    float c[2][NT][4];
    #pragma unroll
    for (int mt = 0; mt < 2; mt++)
        #pragma unroll
        for (int nt = 0; nt < NT; nt++)
            #pragma unroll
            for (int q = 0; q < 4; q++) c[mt][nt][q] = 0.f;

    #pragma unroll
    for (int kc = 0; kc < 128; kc += KC) {
        // A chunk: 128 rows x 64 halves = 1024 8-half chunks, 4/thread
        #pragma unroll
        for (int i = 0; i < 4; i++) {
            int idx = tid + i * 256;
            int row = idx >> 3;
            int ck = idx & 7;
            uint4 v = make_uint4(0u, 0u, 0u, 0u);
            if (block_row + row < NN)
                v = *reinterpret_cast<const uint4*>(
                    &g_a16[(size_t)(block_row + row) * 128 + kc + ck * 8]);
            *reinterpret_cast<uint4*>(&sA[row][(ck ^ (row & 7)) * 8]) = v;
        }
        // B chunk: KC rows x BN halves (from fp32 W), KC*BN/8 chunks
        #pragma unroll
        for (int i = 0; i < (KC * BN / 8) / 256; i++) {
            int idx = tid + i * 256;
            int k = idx / (BN / 8);
            int ck = idx % (BN / 8);
            float4 f0 = *reinterpret_cast<const float4*>(&W[(size_t)(kc + k) * BN + ck * 8]);
            float4 f1 = *reinterpret_cast<const float4*>(&W[(size_t)(kc + k) * BN + ck * 8 + 4]);
            __half2 h0 = __floats2half2_rn(f0.x, f0.y);
            __half2 h1 = __floats2half2_rn(f0.z, f0.w);
            __half2 h2 = __floats2half2_rn(f1.x, f1.y);
            __half2 h3 = __floats2half2_rn(f1.z, f1.w);
            uint4 v;
            v.x = *(unsigned int*)&h0; v.y = *(unsigned int*)&h1;
            v.z = *(unsigned int*)&h2; v.w = *(unsigned int*)&h3;
            *reinterpret_cast<uint4*>(&sB[k][(ck ^ (k & 7)) * 8]) = v;
        }
        __syncthreads();
        #pragma unroll
        for (int k16 = 0; k16 < KC / 16; k16++) {
            unsigned int af[2][4];
            #pragma unroll
            for (int mt = 0; mt < 2; mt++) {
                int row = warp_m * 32 + mt * 16 + (lane & 15);
                int ck = k16 * 2 + (lane >> 4);
                unsigned int addr = smem_u32(&sA[row][(ck ^ (row & 7)) * 8]);
                asm volatile("ldmatrix.sync.aligned.m8n8.x4.shared.b16 {%0,%1,%2,%3}, [%4];"
                    : "=r"(af[mt][0]), "=r"(af[mt][1]), "=r"(af[mt][2]), "=r"(af[mt][3])
                    : "r"(addr));
            }
            unsigned int bf[NT][2];
            #pragma unroll
            for (int nt2 = 0; nt2 < NT / 2; nt2++) {
                int k = k16 * 16 + (lane & 15);
                int ncol = warp_n * WN + nt2 * 16 + (lane >> 4) * 8;
                int ck = ncol >> 3;
                unsigned int addr = smem_u32(&sB[k][(ck ^ (k & 7)) * 8]);
                unsigned int r0, r1, r2, r3;
                asm volatile("ldmatrix.sync.aligned.m8n8.x4.trans.shared.b16 {%0,%1,%2,%3}, [%4];"
                    : "=r"(r0), "=r"(r1), "=r"(r2), "=r"(r3) : "r"(addr));
                bf[nt2 * 2][0] = r0;     bf[nt2 * 2][1] = r1;
                bf[nt2 * 2 + 1][0] = r2; bf[nt2 * 2 + 1][1] = r3;
            }
            #pragma unroll
            for (int mt = 0; mt < 2; mt++)
                #pragma unroll
                for (int nt = 0; nt < NT; nt++)
                    asm volatile(
                        "mma.sync.aligned.m16n8k16.row.col.f32.f16.f16.f32 "
                        "{%0,%1,%2,%3}, {%4,%5,%6,%7}, {%8,%9}, {%0,%1,%2,%3};"
                        : "+f"(c[mt][nt][0]), "+f"(c[mt][nt][1]),
                          "+f"(c[mt][nt][2]), "+f"(c[mt][nt][3])
                        : "r"(af[mt][0]), "r"(af[mt][1]), "r"(af[mt][2]), "r"(af[mt][3]),
                          "r"(bf[nt][0]), "r"(bf[nt][1]));
        }
        __syncthreads();
    }

    // epilogue: fp16 store; D frag: c0,c1 -> (row qr, col qc*2+{0,1}); c2,c3 -> row qr+8
    int qr = lane >> 2;
    int qc = lane & 3;
    #pragma unroll
    for (int mt = 0; mt < 2; mt++) {
        int r0 = block_row + warp_m * 32 + mt * 16 + qr;
        int r1 = r0 + 8;
        #pragma unroll
        for (int nt = 0; nt < NT; nt++) {
            int col = warp_n * WN + nt * 8 + qc * 2;
            if (r0 < NN) {
                __half2 h = __floats2half2_rn(c[mt][nt][0], c[mt][nt][1]);
                *reinterpret_cast<unsigned int*>(&g_h16[(size_t)r0 * BN + col]) =
                    *(unsigned int*)&h;
            }
            if (r1 < NN) {
                __half2 h = __floats2half2_rn(c[mt][nt][2], c[mt][nt][3]);
                *reinterpret_cast<unsigned int*>(&g_h16[(size_t)r1 * BN + col]) =
                    *(unsigned int*)&h;
            }
        }
    }
}

// ---------------- attention scores from h16: as = h@a_s, ad = h@a_d ----------------
__global__ void scores_kernel(const float* __restrict__ avs, const float* __restrict__ avd) {
    int warp = (blockIdx.x * blockDim.x + threadIdx.x) >> 5;
    int lane = threadIdx.x & 31;
    if (warp >= NN) return;
    uint2 raw = reinterpret_cast<const uint2*>(g_h16)[(size_t)warp * 32 + lane];
    float2 f01 = __half22float2(*reinterpret_cast<__half2*>(&raw.x));
    float2 f23 = __half22float2(*reinterpret_cast<__half2*>(&raw.y));
    float4 sv = reinterpret_cast<const float4*>(avs)[lane];
    float4 dv = reinterpret_cast<const float4*>(avd)[lane];
    float s = f01.x * sv.x + f01.y * sv.y + f23.x * sv.z + f23.y * sv.w;
    float d = f01.x * dv.x + f01.y * dv.y + f23.x * dv.z + f23.y * dv.w;
    #pragma unroll
    for (int o = 16; o; o >>= 1) {
        s += __shfl_xor_sync(0xffffffffu, s, o);
        d += __shfl_xor_sync(0xffffffffu, d, o);
    }
    if (lane == 0) { g_as[warp] = s; g_ad[warp] = d; }
}

// ---------------- GAT aggregate: fused softmax, fp16 gather, smem-staged (s,p); fp16 output ----------------
__global__ __launch_bounds__(256)
void gat_agg_kernel(const float* __restrict__ bias) {
    __shared__ float2 s_sp[8][32];
    int warp = (blockIdx.x * blockDim.x + threadIdx.x) >> 5;
    int w = (threadIdx.x >> 5);
    int lane = threadIdx.x & 31;
    if (warp >= NN) return;
    int node = warp;
    int rs = g_rowptr[node], re = g_rowptr[node + 1];
    float adi = g_ad[node];
    float pself = __expf(lrelu(g_as[node] + adi));

    const uint2* h2 = reinterpret_cast<const uint2*>(g_h16);
    uint2 selfraw = h2[(size_t)node * 32 + lane];
    float2 sf01 = __half22float2(*reinterpret_cast<__half2*>(&selfraw.x));
    float2 sf23 = __half22float2(*reinterpret_cast<__half2*>(&selfraw.y));
    float4 acc = make_float4(pself * sf01.x, pself * sf01.y, pself * sf23.x, pself * sf23.y);
    float ssum_l = (lane == 0) ? pself : 0.f;

    for (int base = rs; base < re; base += 32) {
        int j = base + lane;
        int srcv = 0; float pv = 0.f;
        if (j < re) {
            srcv = g_csrc[j];
            pv = __expf(lrelu(g_as[srcv] + adi));
        }
        ssum_l += pv;
        __syncwarp();
        s_sp[w][lane] = make_float2(__int_as_float(srcv), pv);
        __syncwarp();
        int cnt = re - base;
        if (cnt >= 32) {
            #pragma unroll
            for (int t = 0; t < 32; t++) {
                float2 sp = s_sp[w][t];
                int s = __float_as_int(sp.x);
                float p = sp.y;
                uint2 raw = h2[(size_t)s * 32 + lane];
                float2 f01 = __half22float2(*reinterpret_cast<__half2*>(&raw.x));
                float2 f23 = __half22float2(*reinterpret_cast<__half2*>(&raw.y));
                acc.x = fmaf(p, f01.x, acc.x);
                acc.y = fmaf(p, f01.y, acc.y);
                acc.z = fmaf(p, f23.x, acc.z);
                acc.w = fmaf(p, f23.y, acc.w);
            }
        } else {
            for (int t = 0; t < cnt; t++) {
                float2 sp = s_sp[w][t];
                int s = __float_as_int(sp.x);
                float p = sp.y;
                uint2 raw = h2[(size_t)s * 32 + lane];
                float2 f01 = __half22float2(*reinterpret_cast<__half2*>(&raw.x));
                float2 f23 = __half22float2(*reinterpret_cast<__half2*>(&raw.y));
                acc.x = fmaf(p, f01.x, acc.x);
                acc.y = fmaf(p, f01.y, acc.y);
                acc.z = fmaf(p, f23.x, acc.z);
                acc.w = fmaf(p, f23.y, acc.w);
            }
        }
    }
    float ssum = ssum_l;
    #pragma unroll
    for (int o = 16; o; o >>= 1) ssum += __shfl_xor_sync(0xffffffffu, ssum, o);

    float inv = 1.f / ssum;
    float4 bv = reinterpret_cast<const float4*>(bias)[lane];
    float ox = fmaxf(fmaf(acc.x, inv, bv.x), 0.f);
    float oy = fmaxf(fmaf(acc.y, inv, bv.y), 0.f);
    float oz = fmaxf(fmaf(acc.z, inv, bv.z), 0.f);
    float ow = fmaxf(fmaf(acc.w, inv, bv.w), 0.f);
    __half2 ho0 = __floats2half2_rn(ox, oy);
    __half2 ho1 = __floats2half2_rn(oz, ow);
    uint2 st;
    st.x = *(unsigned int*)&ho0;
    st.y = *(unsigned int*)&ho1;
    reinterpret_cast<uint2*>(g_a16)[(size_t)node * 32 + lane] = st;   // next GEMM input
}

// ---------------- GCN aggregate: fp16 gather (row=64 halves), OUT=64, fp32 output ----------------
__global__ __launch_bounds__(256)
void gcn_agg_kernel(const float* __restrict__ bias,
                    float* __restrict__ z) {
    __shared__ float2 s_sp[8][32];
    int warp = (blockIdx.x * blockDim.x + threadIdx.x) >> 5;
    int w = (threadIdx.x >> 5);
    int lane = threadIdx.x & 31;
    if (warp >= NN) return;
    int node = warp;
    int rs = g_rowptr[node], re = g_rowptr[node + 1];
    float di = g_dinv[node];
    const unsigned int* h1 = reinterpret_cast<const unsigned int*>(g_h16);
    unsigned int selfraw = h1[(size_t)node * 32 + lane];
    float2 gv = __half22float2(*reinterpret_cast<__half2*>(&selfraw));
    float nself = di * di;
    float2 acc = make_float2(nself * gv.x, nself * gv.y);
    for (int base = rs; base < re; base += 32) {
        int j = base + lane;
        int srcv = 0; float nrm = 0.f;
        if (j < re) { srcv = g_csrc[j]; nrm = di * g_dinv[srcv]; }
        __syncwarp();
        s_sp[w][lane] = make_float2(__int_as_float(srcv), nrm);
        __syncwarp();
        int cnt = re - base;
        if (cnt >= 32) {
            #pragma unroll
            for (int t = 0; t < 32; t++) {
                float2 sp = s_sp[w][t];
                int s = __float_as_int(sp.x);
                float p = sp.y;
                unsigned int raw = h1[(size_t)s * 32 + lane];
                float2 v = __half22float2(*reinterpret_cast<__half2*>(&raw));
                acc.x = fmaf(p, v.x, acc.x);
                acc.y = fmaf(p, v.y, acc.y);
            }
        } else {
            for (int t = 0; t < cnt; t++) {
                float2 sp = s_sp[w][t];
                int s = __float_as_int(sp.x);
                float p = sp.y;
                unsigned int raw = h1[(size_t)s * 32 + lane];
                float2 v = __half22float2(*reinterpret_cast<__half2*>(&raw));
                acc.x = fmaf(p, v.x, acc.x);
                acc.y = fmaf(p, v.y, acc.y);
            }
        }
    }
    float2 bv = reinterpret_cast<const float2*>(bias)[lane];
    reinterpret_cast<float2*>(z)[(size_t)node * 32 + lane] =
        make_float2(acc.x + bv.x, acc.y + bv.y);
}

// ---------------- decode + re-zero of deg/cursor ----------------
__global__ void decode_kernel(const int* __restrict__ eli, float* __restrict__ out) {
    if (blockIdx.x >= DEC_BLOCKS) {
        int i = (blockIdx.x - DEC_BLOCKS) * 256 + threadIdx.x;
        for (int k = i; k < NN; k += ZERO_BLOCKS * 256) { g_deg[k] = 0; g_cursor[k] = 0; }
        return;
    }
    int gtid = blockIdx.x * blockDim.x + threadIdx.x;
    int warp = gtid >> 5;
    int lane = threadIdx.x & 31;
    int sub = lane >> 3, l8 = lane & 7;
    int e = warp * 4 + sub;
    if (e >= NLL) return;
    int a = eli[e];
    int b = eli[NLL + e];
    const float4* z4 = reinterpret_cast<const float4*>(g_zbuf);
    float4 va0 = z4[(size_t)a * 16 + l8];
    float4 va1 = z4[(size_t)a * 16 + 8 + l8];
    float4 vb0 = z4[(size_t)b * 16 + l8];
    float4 vb1 = z4[(size_t)b * 16 + 8 + l8];
    float dot = va0.x * vb0.x + va0.y * vb0.y + va0.z * vb0.z + va0.w * vb0.w
              + va1.x * vb1.x + va1.y * vb1.y + va1.z * vb1.z + va1.w * vb1.w;
    dot += __shfl_xor_sync(0xffffffffu, dot, 4);
    dot += __shfl_xor_sync(0xffffffffu, dot, 2);
    dot += __shfl_xor_sync(0xffffffffu, dot, 1);
    if (l8 == 0) out[e] = dot;
}

// ---------------- launch ----------------
extern "C" void kernel_launch(void* const* d_in, const int* in_sizes, int n_in,
                              void* d_out, int out_size) {
    const float* x   = (const float*)d_in[0];
    const int*   ei  = (const int*)d_in[1];          // [2,E]
    const int*   eli = (const int*)d_in[2];          // [2,NL]
    const float* W1  = (const float*)d_in[3];
    const float* a1s = (const float*)d_in[4];
    const float* a1d = (const float*)d_in[5];
    const float* b1  = (const float*)d_in[6];
    const float* W2  = (const float*)d_in[7];
    const float* a2s = (const float*)d_in[8];
    const float* a2d = (const float*)d_in[9];
    const float* b2  = (const float*)d_in[10];
    const float* W3  = (const float*)d_in[11];
    const float* a3s = (const float*)d_in[12];
    const float* a3d = (const float*)d_in[13];
    const float* b3  = (const float*)d_in[14];
    const float* W4  = (const float*)d_in[15];
    const float* b4  = (const float*)d_in[16];
    float* out = (float*)d_out;

    const int* e_src = ei;
    const int* e_dst = ei + EE;

    float* zbuf;
    cudaGetSymbolAddress((void**)&zbuf, g_zbuf);

    const int TB = 256;
    int node_warp_blocks = (NN * 32 + TB - 1) / TB;

    // 0: degree count + x->fp16
    prep_kernel<<<E4_BLOCKS + CVT_BLOCKS, TB>>>(x, e_dst);
    // 1: per-block local scan (+dinv, +bsum)
    scan_partial_kernel<<<NBLK, SCAN_B>>>();
    // 2: CSR fill + rowptr finalize
    fill_finalize_kernel<<<E4_BLOCKS + FIN_BLOCKS, TB>>>(e_src, e_dst);

    // layer 1 (launch 3 = hgemm, profiled)
    hgemm_kernel<HIDD><<<GEMM_BLOCKS, 256>>>(W1);
    scores_kernel<<<node_warp_blocks, TB>>>(a1s, a1d);
    gat_agg_kernel<<<node_warp_blocks, TB>>>(b1);

    // layer 2
    hgemm_kernel<HIDD><<<GEMM_BLOCKS, 256>>>(W2);
    scores_kernel<<<node_warp_blocks, TB>>>(a2s, a2d);
    gat_agg_kernel<<<node_warp_blocks, TB>>>(b2);

    // layer 3
    hgemm_kernel<HIDD><<<GEMM_BLOCKS, 256>>>(W3);
    scores_kernel<<<node_warp_blocks, TB>>>(a3s, a3d);
    gat_agg_kernel<<<node_warp_blocks, TB>>>(b3);

    // GCN
    hgemm_kernel<DOUT><<<GEMM_BLOCKS, 256>>>(W4);
    gcn_agg_kernel<<<node_warp_blocks, TB>>>(b4, zbuf);

    // decode + re-zero deg/cursor
    decode_kernel<<<DEC_BLOCKS + ZERO_BLOCKS, TB>>>(eli, out);
}

// round 16
// speedup vs baseline: 1.4291x; 1.0519x over previous
#include <cuda_runtime.h>
#include <cuda_fp16.h>
#include <math.h>

#define NN   50000
#define EE   1600000
#define DIN  128
#define HIDD 128
#define DOUT 64
#define NLL  200000
#define NEG  0.2f

#define SCAN_B 512
#define NBLK   ((NN + SCAN_B - 1) / SCAN_B)   // 98
#define GEMM_BLOCKS ((NN + 127) / 128)        // 391
#define E4_BLOCKS   ((EE / 4 + 255) / 256)    // 1563
#define FIN_BLOCKS  ((NN + 255) / 256)        // 196
#define CVT_BLOCKS  ((NN * 128 / 8 + 255) / 256)  // 3125
#define DEC_BLOCKS  (((NLL + 3) / 4 * 32 + 255) / 256)
#define ZERO_BLOCKS 32

// ---------------- scratch (device globals; no allocation allowed) ----------------
__device__ __half g_a16[NN * HIDD];    // fp16 GEMM input (x16 or agg output)
__device__ __half g_h16[NN * HIDD];    // fp16 GEMM output (gather/scores source)
__device__ __half g_z16[NN * DOUT];    // fp16 final embeddings (decode source)
__device__ float  g_as[NN];
__device__ float  g_ad[NN];
__device__ float  g_dinv[NN];
__device__ int    g_deg[NN];       // zero-initialized at load; re-zeroed by decode
__device__ int    g_cursor[NN];    // same
__device__ int    g_rowloc[NN];
__device__ int    g_rowptr[NN + 1];
__device__ int    g_csrc[EE];
__device__ int    g_bsum[NBLK];

__device__ __forceinline__ float lrelu(float v) { return v > 0.f ? v : NEG * v; }
__device__ __forceinline__ unsigned int smem_u32(const void* p) {
    return (unsigned int)__cvta_generic_to_shared(p);
}

// ---------------- launch 0: degree count + x -> fp16 conversion ----------------
__global__ void prep_kernel(const float* __restrict__ x, const int* __restrict__ edst) {
    int b = blockIdx.x;
    int tid = threadIdx.x;
    if (b < E4_BLOCKS) {
        int i = b * 256 + tid;
        if (i < EE / 4) {
            int4 d = reinterpret_cast<const int4*>(edst)[i];
            atomicAdd(&g_deg[d.x], 1);
            atomicAdd(&g_deg[d.y], 1);
            atomicAdd(&g_deg[d.z], 1);
            atomicAdd(&g_deg[d.w], 1);
        }
        return;
    }
    int i = (b - E4_BLOCKS) * 256 + tid;     // each converts 8 floats
    if (i < NN * 128 / 8) {
        float4 f0 = reinterpret_cast<const float4*>(x)[i * 2];
        float4 f1 = reinterpret_cast<const float4*>(x)[i * 2 + 1];
        __half2 h0 = __floats2half2_rn(f0.x, f0.y);
        __half2 h1 = __floats2half2_rn(f0.z, f0.w);
        __half2 h2 = __floats2half2_rn(f1.x, f1.y);
        __half2 h3 = __floats2half2_rn(f1.z, f1.w);
        uint4 v;
        v.x = *(unsigned int*)&h0; v.y = *(unsigned int*)&h1;
        v.z = *(unsigned int*)&h2; v.w = *(unsigned int*)&h3;
        reinterpret_cast<uint4*>(g_a16)[i] = v;
    }
}

// ---------------- launch 1: per-block local scan (+bsum, +dinv) ----------------
__global__ void scan_partial_kernel() {
    __shared__ int ws[SCAN_B / 32];
    int tid = threadIdx.x;
    int lane = tid & 31, wid = tid >> 5;
    int i = blockIdx.x * SCAN_B + tid;
    int v = (i < NN) ? g_deg[i] : 0;
    if (i < NN) g_dinv[i] = rsqrtf((float)(v + 1));
    int x = v;
    #pragma unroll
    for (int o = 1; o < 32; o <<= 1) {
        int y = __shfl_up_sync(0xffffffffu, x, o);
        if (lane >= o) x += y;
    }
    if (lane == 31) ws[wid] = x;
    __syncthreads();
    if (tid < 32) {
        int w = (tid < SCAN_B / 32) ? ws[tid] : 0;
        #pragma unroll
        for (int o = 1; o < SCAN_B / 32; o <<= 1) {
            int y = __shfl_up_sync(0xffffffffu, w, o);
            if (tid >= o) w += y;
        }
        if (tid < SCAN_B / 32) ws[tid] = w;
    }
    __syncthreads();
    int pref = wid ? ws[wid - 1] : 0;
    int incl = x + pref;
    if (i < NN) g_rowloc[i] = incl - v;
    if (tid == SCAN_B - 1) g_bsum[blockIdx.x] = incl;
}

__device__ __forceinline__ void block_boff(int* s_boff, int* s_ws) {
    int tid = threadIdx.x;
    if (tid < 128) {
        int lane = tid & 31, w4 = tid >> 5;
        int v = (tid < NBLK) ? g_bsum[tid] : 0;
        int x = v;
        #pragma unroll
        for (int o = 1; o < 32; o <<= 1) {
            int y = __shfl_up_sync(0xffffffffu, x, o);
            if (lane >= o) x += y;
        }
        if (lane == 31) s_ws[w4] = x;
    }
    __syncthreads();
    if (tid < 32) {
        int w = (tid < 4) ? s_ws[tid] : 0;
        #pragma unroll
        for (int o = 1; o < 4; o <<= 1) {
            int y = __shfl_up_sync(0xffffffffu, w, o);
            if (tid >= o) w += y;
        }
        if (tid < 4) s_ws[tid] = w;
    }
    __syncthreads();
    if (tid < 128) {
        int lane = tid & 31, w4 = tid >> 5;
        int v = (tid < NBLK) ? g_bsum[tid] : 0;
        int x = v;
        #pragma unroll
        for (int o = 1; o < 32; o <<= 1) {
            int y = __shfl_up_sync(0xffffffffu, x, o);
            if (lane >= o) x += y;
        }
        int pref = w4 ? s_ws[w4 - 1] : 0;
        if (tid < NBLK) s_boff[tid] = x + pref - v;
    }
    __syncthreads();
}

// ---------------- launch 2: CSR fill + rowptr finalize ----------------
__global__ void fill_finalize_kernel(const int* __restrict__ src, const int* __restrict__ dst) {
    __shared__ int s_boff[NBLK];
    __shared__ int s_ws[4];
    block_boff(s_boff, s_ws);
    int tid = threadIdx.x;
    int b = blockIdx.x;
    if (b < E4_BLOCKS) {
        int i = b * 256 + tid;
        if (i < EE / 4) {
            int4 s = reinterpret_cast<const int4*>(src)[i];
            int4 d = reinterpret_cast<const int4*>(dst)[i];
            int p;
            p = atomicAdd(&g_cursor[d.x], 1); g_csrc[g_rowloc[d.x] + s_boff[d.x >> 9] + p] = s.x;
            p = atomicAdd(&g_cursor[d.y], 1); g_csrc[g_rowloc[d.y] + s_boff[d.y >> 9] + p] = s.y;
            p = atomicAdd(&g_cursor[d.z], 1); g_csrc[g_rowloc[d.z] + s_boff[d.z >> 9] + p] = s.z;
            p = atomicAdd(&g_cursor[d.w], 1); g_csrc[g_rowloc[d.w] + s_boff[d.w >> 9] + p] = s.w;
        }
    } else {
        int i = (b - E4_BLOCKS) * 256 + tid;
        if (i < NN) g_rowptr[i] = g_rowloc[i] + s_boff[i >> 9];
        if (b == E4_BLOCKS && tid == 0) g_rowptr[NN] = EE;
    }
}

// ---------------- HGEMM: g_h16[M,BN] = g_a16[M,128] * W[128,BN], mma.sync fp16->fp32 ----------------
// Tile 128xBN, 8 warps (warp tile 32 x BN/2). K staged in 2 chunks of 64.
// __launch_bounds__(256,2): cap 128 regs -> 2 blocks/SM (was 140 regs / occ 12%).
template<int BN>
__global__ __launch_bounds__(256, 2)
void hgemm_kernel(const float* __restrict__ W) {
    constexpr int KC = 64;
    constexpr int WN = BN / 2;
    constexpr int NT = WN / 8;
    __shared__ __align__(16) __half sA[128][KC];
    __shared__ __align__(16) __half sB[KC][BN];
    int tid = threadIdx.x;
    int wid = tid >> 5, lane = tid & 31;
    int warp_m = wid & 3, warp_n = wid >> 2;
    int block_row = blockIdx.x * 128;

    float c[2][NT][4];
    #pragma unroll
    for (int mt = 0; mt < 2; mt++)
        #pragma unroll
        for (int nt = 0; nt < NT; nt++)
            #pragma unroll
            for (int q = 0; q < 4; q++) c[mt][nt][q] = 0.f;

    #pragma unroll
    for (int kc = 0; kc < 128; kc += KC) {
        #pragma unroll
        for (int i = 0; i < 4; i++) {
            int idx = tid + i * 256;
            int row = idx >> 3;
            int ck = idx & 7;
            uint4 v = make_uint4(0u, 0u, 0u, 0u);
            if (block_row + row < NN)
                v = *reinterpret_cast<const uint4*>(
                    &g_a16[(size_t)(block_row + row) * 128 + kc + ck * 8]);
            *reinterpret_cast<uint4*>(&sA[row][(ck ^ (row & 7)) * 8]) = v;
        }
        #pragma unroll
        for (int i = 0; i < (KC * BN / 8) / 256; i++) {
            int idx = tid + i * 256;
            int k = idx / (BN / 8);
            int ck = idx % (BN / 8);
            float4 f0 = *reinterpret_cast<const float4*>(&W[(size_t)(kc + k) * BN + ck * 8]);
            float4 f1 = *reinterpret_cast<const float4*>(&W[(size_t)(kc + k) * BN + ck * 8 + 4]);
            __half2 h0 = __floats2half2_rn(f0.x, f0.y);
            __half2 h1 = __floats2half2_rn(f0.z, f0.w);
            __half2 h2 = __floats2half2_rn(f1.x, f1.y);
            __half2 h3 = __floats2half2_rn(f1.z, f1.w);
            uint4 v;
            v.x = *(unsigned int*)&h0; v.y = *(unsigned int*)&h1;
            v.z = *(unsigned int*)&h2; v.w = *(unsigned int*)&h3;
            *reinterpret_cast<uint4*>(&sB[k][(ck ^ (k & 7)) * 8]) = v;
        }
        __syncthreads();
        #pragma unroll
        for (int k16 = 0; k16 < KC / 16; k16++) {
            unsigned int af[2][4];
            #pragma unroll
            for (int mt = 0; mt < 2; mt++) {
                int row = warp_m * 32 + mt * 16 + (lane & 15);
                int ck = k16 * 2 + (lane >> 4);
                unsigned int addr = smem_u32(&sA[row][(ck ^ (row & 7)) * 8]);
                asm volatile("ldmatrix.sync.aligned.m8n8.x4.shared.b16 {%0,%1,%2,%3}, [%4];"
                    : "=r"(af[mt][0]), "=r"(af[mt][1]), "=r"(af[mt][2]), "=r"(af[mt][3])
                    : "r"(addr));
            }
            unsigned int bf[NT][2];
            #pragma unroll
            for (int nt2 = 0; nt2 < NT / 2; nt2++) {
                int k = k16 * 16 + (lane & 15);
                int ncol = warp_n * WN + nt2 * 16 + (lane >> 4) * 8;
                int ck = ncol >> 3;
                unsigned int addr = smem_u32(&sB[k][(ck ^ (k & 7)) * 8]);
                unsigned int r0, r1, r2, r3;
                asm volatile("ldmatrix.sync.aligned.m8n8.x4.trans.shared.b16 {%0,%1,%2,%3}, [%4];"
                    : "=r"(r0), "=r"(r1), "=r"(r2), "=r"(r3) : "r"(addr));
                bf[nt2 * 2][0] = r0;     bf[nt2 * 2][1] = r1;
                bf[nt2 * 2 + 1][0] = r2; bf[nt2 * 2 + 1][1] = r3;
            }
            #pragma unroll
            for (int mt = 0; mt < 2; mt++)
                #pragma unroll
                for (int nt = 0; nt < NT; nt++)
                    asm volatile(
                        "mma.sync.aligned.m16n8k16.row.col.f32.f16.f16.f32 "
                        "{%0,%1,%2,%3}, {%4,%5,%6,%7}, {%8,%9}, {%0,%1,%2,%3};"
                        : "+f"(c[mt][nt][0]), "+f"(c[mt][nt][1]),
                          "+f"(c[mt][nt][2]), "+f"(c[mt][nt][3])
                        : "r"(af[mt][0]), "r"(af[mt][1]), "r"(af[mt][2]), "r"(af[mt][3]),
                          "r"(bf[nt][0]), "r"(bf[nt][1]));
        }
        __syncthreads();
    }

    int qr = lane >> 2;
    int qc = lane & 3;
    #pragma unroll
    for (int mt = 0; mt < 2; mt++) {
        int r0 = block_row + warp_m * 32 + mt * 16 + qr;
        int r1 = r0 + 8;
        #pragma unroll
        for (int nt = 0; nt < NT; nt++) {
            int col = warp_n * WN + nt * 8 + qc * 2;
            if (r0 < NN) {
                __half2 h = __floats2half2_rn(c[mt][nt][0], c[mt][nt][1]);
                *reinterpret_cast<unsigned int*>(&g_h16[(size_t)r0 * BN + col]) =
                    *(unsigned int*)&h;
            }
            if (r1 < NN) {
                __half2 h = __floats2half2_rn(c[mt][nt][2], c[mt][nt][3]);
                *reinterpret_cast<unsigned int*>(&g_h16[(size_t)r1 * BN + col]) =
                    *(unsigned int*)&h;
            }
        }
    }
}

// ---------------- attention scores from h16: as = h@a_s, ad = h@a_d ----------------
__global__ void scores_kernel(const float* __restrict__ avs, const float* __restrict__ avd) {
    int warp = (blockIdx.x * blockDim.x + threadIdx.x) >> 5;
    int lane = threadIdx.x & 31;
    if (warp >= NN) return;
    uint2 raw = reinterpret_cast<const uint2*>(g_h16)[(size_t)warp * 32 + lane];
    float2 f01 = __half22float2(*reinterpret_cast<__half2*>(&raw.x));
    float2 f23 = __half22float2(*reinterpret_cast<__half2*>(&raw.y));
    float4 sv = reinterpret_cast<const float4*>(avs)[lane];
    float4 dv = reinterpret_cast<const float4*>(avd)[lane];
    float s = f01.x * sv.x + f01.y * sv.y + f23.x * sv.z + f23.y * sv.w;
    float d = f01.x * dv.x + f01.y * dv.y + f23.x * dv.z + f23.y * dv.w;
    #pragma unroll
    for (int o = 16; o; o >>= 1) {
        s += __shfl_xor_sync(0xffffffffu, s, o);
        d += __shfl_xor_sync(0xffffffffu, d, o);
    }
    if (lane == 0) { g_as[warp] = s; g_ad[warp] = d; }
}

// ---------------- GAT aggregate: fused softmax, fp16 gather, smem-staged (s,p); fp16 output ----------------
__global__ __launch_bounds__(256)
void gat_agg_kernel(const float* __restrict__ bias) {
    __shared__ float2 s_sp[8][32];
    int warp = (blockIdx.x * blockDim.x + threadIdx.x) >> 5;
    int w = (threadIdx.x >> 5);
    int lane = threadIdx.x & 31;
    if (warp >= NN) return;
    int node = warp;
    int rs = g_rowptr[node], re = g_rowptr[node + 1];
    float adi = g_ad[node];
    float pself = __expf(lrelu(g_as[node] + adi));

    const uint2* h2 = reinterpret_cast<const uint2*>(g_h16);
    uint2 selfraw = h2[(size_t)node * 32 + lane];
    float2 sf01 = __half22float2(*reinterpret_cast<__half2*>(&selfraw.x));
    float2 sf23 = __half22float2(*reinterpret_cast<__half2*>(&selfraw.y));
    float4 acc = make_float4(pself * sf01.x, pself * sf01.y, pself * sf23.x, pself * sf23.y);
    float ssum_l = (lane == 0) ? pself : 0.f;

    for (int base = rs; base < re; base += 32) {
        int j = base + lane;
        int srcv = 0; float pv = 0.f;
        if (j < re) {
            srcv = g_csrc[j];
            pv = __expf(lrelu(g_as[srcv] + adi));
        }
        ssum_l += pv;
        __syncwarp();
        s_sp[w][lane] = make_float2(__int_as_float(srcv), pv);
        __syncwarp();
        int cnt = re - base;
        if (cnt >= 32) {
            #pragma unroll
            for (int t = 0; t < 32; t++) {
                float2 sp = s_sp[w][t];
                int s = __float_as_int(sp.x);
                float p = sp.y;
                uint2 raw = h2[(size_t)s * 32 + lane];
                float2 f01 = __half22float2(*reinterpret_cast<__half2*>(&raw.x));
                float2 f23 = __half22float2(*reinterpret_cast<__half2*>(&raw.y));
                acc.x = fmaf(p, f01.x, acc.x);
                acc.y = fmaf(p, f01.y, acc.y);
                acc.z = fmaf(p, f23.x, acc.z);
                acc.w = fmaf(p, f23.y, acc.w);
            }
        } else {
            for (int t = 0; t < cnt; t++) {
                float2 sp = s_sp[w][t];
                int s = __float_as_int(sp.x);
                float p = sp.y;
                uint2 raw = h2[(size_t)s * 32 + lane];
                float2 f01 = __half22float2(*reinterpret_cast<__half2*>(&raw.x));
                float2 f23 = __half22float2(*reinterpret_cast<__half2*>(&raw.y));
                acc.x = fmaf(p, f01.x, acc.x);
                acc.y = fmaf(p, f01.y, acc.y);
                acc.z = fmaf(p, f23.x, acc.z);
                acc.w = fmaf(p, f23.y, acc.w);
            }
        }
    }
    float ssum = ssum_l;
    #pragma unroll
    for (int o = 16; o; o >>= 1) ssum += __shfl_xor_sync(0xffffffffu, ssum, o);

    float inv = 1.f / ssum;
    float4 bv = reinterpret_cast<const float4*>(bias)[lane];
    float ox = fmaxf(fmaf(acc.x, inv, bv.x), 0.f);
    float oy = fmaxf(fmaf(acc.y, inv, bv.y), 0.f);
    float oz = fmaxf(fmaf(acc.z, inv, bv.z), 0.f);
    float ow = fmaxf(fmaf(acc.w, inv, bv.w), 0.f);
    __half2 ho0 = __floats2half2_rn(ox, oy);
    __half2 ho1 = __floats2half2_rn(oz, ow);
    uint2 st;
    st.x = *(unsigned int*)&ho0;
    st.y = *(unsigned int*)&ho1;
    reinterpret_cast<uint2*>(g_a16)[(size_t)node * 32 + lane] = st;   // next GEMM input
}

// ---------------- GCN aggregate: fp16 gather, fp16 z output (decode source) ----------------
__global__ __launch_bounds__(256)
void gcn_agg_kernel(const float* __restrict__ bias) {
    __shared__ float2 s_sp[8][32];
    int warp = (blockIdx.x * blockDim.x + threadIdx.x) >> 5;
    int w = (threadIdx.x >> 5);
    int lane = threadIdx.x & 31;
    if (warp >= NN) return;
    int node = warp;
    int rs = g_rowptr[node], re = g_rowptr[node + 1];
    float di = g_dinv[node];
    const unsigned int* h1 = reinterpret_cast<const unsigned int*>(g_h16);
    unsigned int selfraw = h1[(size_t)node * 32 + lane];
    float2 gv = __half22float2(*reinterpret_cast<__half2*>(&selfraw));
    float nself = di * di;
    float2 acc = make_float2(nself * gv.x, nself * gv.y);
    for (int base = rs; base < re; base += 32) {
        int j = base + lane;
        int srcv = 0; float nrm = 0.f;
        if (j < re) { srcv = g_csrc[j]; nrm = di * g_dinv[srcv]; }
        __syncwarp();
        s_sp[w][lane] = make_float2(__int_as_float(srcv), nrm);
        __syncwarp();
        int cnt = re - base;
        if (cnt >= 32) {
            #pragma unroll
            for (int t = 0; t < 32; t++) {
                float2 sp = s_sp[w][t];
                int s = __float_as_int(sp.x);
                float p = sp.y;
                unsigned int raw = h1[(size_t)s * 32 + lane];
                float2 v = __half22float2(*reinterpret_cast<__half2*>(&raw));
                acc.x = fmaf(p, v.x, acc.x);
                acc.y = fmaf(p, v.y, acc.y);
            }
        } else {
            for (int t = 0; t < cnt; t++) {
                float2 sp = s_sp[w][t];
                int s = __float_as_int(sp.x);
                float p = sp.y;
                unsigned int raw = h1[(size_t)s * 32 + lane];
                float2 v = __half22float2(*reinterpret_cast<__half2*>(&raw));
                acc.x = fmaf(p, v.x, acc.x);
                acc.y = fmaf(p, v.y, acc.y);
            }
        }
    }
    float2 bv = reinterpret_cast<const float2*>(bias)[lane];
    __half2 hz = __floats2half2_rn(acc.x + bv.x, acc.y + bv.y);
    reinterpret_cast<unsigned int*>(g_z16)[(size_t)node * 32 + lane] =
        *(unsigned int*)&hz;
}

// ---------------- decode (fp16 z): out[e] = dot(z[a], z[b]), 8 lanes/edge ----------------
__global__ void decode_kernel(const int* __restrict__ eli, float* __restrict__ out) {
    if (blockIdx.x >= DEC_BLOCKS) {
        int i = (blockIdx.x - DEC_BLOCKS) * 256 + threadIdx.x;
        for (int k = i; k < NN; k += ZERO_BLOCKS * 256) { g_deg[k] = 0; g_cursor[k] = 0; }
        return;
    }
    int gtid = blockIdx.x * blockDim.x + threadIdx.x;
    int warp = gtid >> 5;
    int lane = threadIdx.x & 31;
    int sub = lane >> 3, l8 = lane & 7;
    int e = warp * 4 + sub;
    if (e >= NLL) return;
    int a = eli[e];
    int b = eli[NLL + e];
    const uint4* z8 = reinterpret_cast<const uint4*>(g_z16);   // 8 halves per uint4
    uint4 va = z8[(size_t)a * 8 + l8];
    uint4 vb = z8[(size_t)b * 8 + l8];
    float2 a0 = __half22float2(*reinterpret_cast<__half2*>(&va.x));
    float2 a1 = __half22float2(*reinterpret_cast<__half2*>(&va.y));
    float2 a2 = __half22float2(*reinterpret_cast<__half2*>(&va.z));
    float2 a3 = __half22float2(*reinterpret_cast<__half2*>(&va.w));
    float2 b0 = __half22float2(*reinterpret_cast<__half2*>(&vb.x));
    float2 b1 = __half22float2(*reinterpret_cast<__half2*>(&vb.y));
    float2 b2 = __half22float2(*reinterpret_cast<__half2*>(&vb.z));
    float2 b3 = __half22float2(*reinterpret_cast<__half2*>(&vb.w));
    float dot = a0.x * b0.x + a0.y * b0.y + a1.x * b1.x + a1.y * b1.y
              + a2.x * b2.x + a2.y * b2.y + a3.x * b3.x + a3.y * b3.y;
    dot += __shfl_xor_sync(0xffffffffu, dot, 4);
    dot += __shfl_xor_sync(0xffffffffu, dot, 2);
    dot += __shfl_xor_sync(0xffffffffu, dot, 1);
    if (l8 == 0) out[e] = dot;
}

// ---------------- launch ----------------
extern "C" void kernel_launch(void* const* d_in, const int* in_sizes, int n_in,
                              void* d_out, int out_size) {
    const float* x   = (const float*)d_in[0];
    const int*   ei  = (const int*)d_in[1];          // [2,E]
    const int*   eli = (const int*)d_in[2];          // [2,NL]
    const float* W1  = (const float*)d_in[3];
    const float* a1s = (const float*)d_in[4];
    const float* a1d = (const float*)d_in[5];
    const float* b1  = (const float*)d_in[6];
    const float* W2  = (const float*)d_in[7];
    const float* a2s = (const float*)d_in[8];
    const float* a2d = (const float*)d_in[9];
    const float* b2  = (const float*)d_in[10];
    const float* W3  = (const float*)d_in[11];
    const float* a3s = (const float*)d_in[12];
    const float* a3d = (const float*)d_in[13];
    const float* b3  = (const float*)d_in[14];
    const float* W4  = (const float*)d_in[15];
    const float* b4  = (const float*)d_in[16];
    float* out = (float*)d_out;

    const int* e_src = ei;
    const int* e_dst = ei + EE;

    const int TB = 256;
    int node_warp_blocks = (NN * 32 + TB - 1) / TB;

    // 0: degree count + x->fp16
    prep_kernel<<<E4_BLOCKS + CVT_BLOCKS, TB>>>(x, e_dst);
    // 1: per-block local scan (+dinv, +bsum)
    scan_partial_kernel<<<NBLK, SCAN_B>>>();
    // 2: CSR fill + rowptr finalize
    fill_finalize_kernel<<<E4_BLOCKS + FIN_BLOCKS, TB>>>(e_src, e_dst);

    // layer 1 (launch 3 = hgemm, profiled)
    hgemm_kernel<HIDD><<<GEMM_BLOCKS, 256>>>(W1);
    scores_kernel<<<node_warp_blocks, TB>>>(a1s, a1d);
    gat_agg_kernel<<<node_warp_blocks, TB>>>(b1);

    // layer 2
    hgemm_kernel<HIDD><<<GEMM_BLOCKS, 256>>>(W2);
    scores_kernel<<<node_warp_blocks, TB>>>(a2s, a2d);
    gat_agg_kernel<<<node_warp_blocks, TB>>>(b2);

    // layer 3
    hgemm_kernel<HIDD><<<GEMM_BLOCKS, 256>>>(W3);
    scores_kernel<<<node_warp_blocks, TB>>>(a3s, a3d);
    gat_agg_kernel<<<node_warp_blocks, TB>>>(b3);

    // GCN
    hgemm_kernel<DOUT><<<GEMM_BLOCKS, 256>>>(W4);
    gcn_agg_kernel<<<node_warp_blocks, TB>>>(b4);

    // decode + re-zero deg/cursor
    decode_kernel<<<DEC_BLOCKS + ZERO_BLOCKS, TB>>>(eli, out);
}